// round 7
// baseline (speedup 1.0000x reference)
#include <cuda_runtime.h>
#include <cuda_bf16.h>
#include <cstdint>

// Dims fixed: B=4, S=256, D_MODEL=2048, H=256, HEAD_DIM=8; M = B*S = 1024.
#define M_DIM 1024
#define N_DIM 2048
#define K_DIM 2048
#define HEADS 256

// ---------------- scratch ----------------
__device__ float g_q  [M_DIM * N_DIM];
__device__ float g_k  [M_DIM * N_DIM];
__device__ float g_v  [M_DIM * N_DIM];
__device__ float g_att[M_DIM * N_DIM];

// ---------------- tf32 tensor-core GEMM (mma.sync) ----------------
// C[M,N] = A[M,K] @ W[K,N] + bias. Block 128x128, BK=16, 256 thr (8 warps 2x4),
// warp tile 64x32 (4x4 m16n8k8). A smem m-major [128][20] (pad->conflict-free
// frag LDS AND float4 STS). B smem k-major [16][136]. One sync/iter,
// 2 CTAs/SM via launch_bounds.
#define BK 16
#define ASTR 20
#define BSTR 136

__device__ __forceinline__ unsigned f2tf(float x) {
    unsigned r;
    asm("cvt.rna.tf32.f32 %0, %1;" : "=r"(r) : "f"(x));
    return r;
}
__device__ __forceinline__ float f2tff(float x) {
    float r;
    asm("cvt.rna.tf32.f32 %0, %1;" : "=f"(r) : "f"(x));
    return r;
}

__device__ __forceinline__ void mma_tf32(float* c,
                                         unsigned a0, unsigned a1, unsigned a2, unsigned a3,
                                         unsigned b0, unsigned b1)
{
    asm volatile(
        "mma.sync.aligned.m16n8k8.row.col.f32.tf32.tf32.f32 "
        "{%0,%1,%2,%3}, {%4,%5,%6,%7}, {%8,%9}, {%0,%1,%2,%3};\n"
        : "+f"(c[0]), "+f"(c[1]), "+f"(c[2]), "+f"(c[3])
        : "r"(a0), "r"(a1), "r"(a2), "r"(a3), "r"(b0), "r"(b1));
}

__device__ __forceinline__ void gemm_body(const float* __restrict__ A,
                                          const float* __restrict__ W,
                                          const float* __restrict__ bias,
                                          float* __restrict__ C)
{
    __shared__ float As[2][128][ASTR];   // m-major: As[b][m][k]
    __shared__ float Bs[2][BK][BSTR];    // k-major: Bs[b][k][n]

    const int tid  = threadIdx.x;
    const int lane = tid & 31;
    const int wid  = tid >> 5;
    const int wm   = wid >> 2;          // 0..1 -> warp M base wm*64
    const int wn   = wid & 3;           // 0..3 -> warp N base wn*32
    const int lr   = lane >> 2;         // 0..7
    const int lc   = lane & 3;          // 0..3
    const int bm   = blockIdx.y * 128;
    const int bn   = blockIdx.x * 128;

    // A loader: row ra (and ra+64), cols cgA*4..+3 (float4). Warp = 32 consecutive
    // rows, fixed cgA -> STS phases of 8 consecutive rows: banks r*20+c distinct.
    const int ra  = tid & 63;
    const int cgA = (tid >> 6) * 4;     // 0,4,8,12
    // B loader: row rb, cols cb and cb+64 (float4). Conflict-free with BSTR=136.
    const int rb = tid >> 4;            // 0..15
    const int cb = (tid & 15) * 4;      // 0..60

    const float* Ap = A + (size_t)(bm + ra) * K_DIM + cgA;
    const float* Bp = W + (size_t)rb * N_DIM + bn + cb;

    float c[4][4][4];
    #pragma unroll
    for (int i = 0; i < 4; i++)
        #pragma unroll
        for (int j = 0; j < 4; j++)
            #pragma unroll
            for (int r = 0; r < 4; r++) c[i][j][r] = 0.0f;

    float4 va0, va1, vb0, vb1;

    // prologue: load chunk 0
    va0 = *(const float4*)(Ap);
    va1 = *(const float4*)(Ap + (size_t)64 * K_DIM);
    vb0 = *(const float4*)(Bp);
    vb1 = *(const float4*)(Bp + 64);

    const int NK = K_DIM / BK;   // 128
    for (int kt = 0; kt < NK; kt++) {
        const int cur = kt & 1;

        // STS (tf32-round on the fly), then ONE sync
        {
            float4 a0, a1, b0, b1;
            a0.x = f2tff(va0.x); a0.y = f2tff(va0.y); a0.z = f2tff(va0.z); a0.w = f2tff(va0.w);
            a1.x = f2tff(va1.x); a1.y = f2tff(va1.y); a1.z = f2tff(va1.z); a1.w = f2tff(va1.w);
            b0.x = f2tff(vb0.x); b0.y = f2tff(vb0.y); b0.z = f2tff(vb0.z); b0.w = f2tff(vb0.w);
            b1.x = f2tff(vb1.x); b1.y = f2tff(vb1.y); b1.z = f2tff(vb1.z); b1.w = f2tff(vb1.w);
            *(float4*)&As[cur][ra][cgA]      = a0;
            *(float4*)&As[cur][ra + 64][cgA] = a1;
            *(float4*)&Bs[cur][rb][cb]       = b0;
            *(float4*)&Bs[cur][rb][cb + 64]  = b1;
        }
        __syncthreads();

        // prefetch next chunk (overlaps compute)
        if (kt + 1 < NK) {
            const int kc = (kt + 1) * BK;
            va0 = *(const float4*)(Ap + kc);
            va1 = *(const float4*)(Ap + (size_t)64 * K_DIM + kc);
            vb0 = *(const float4*)(Bp + (size_t)kc * N_DIM);
            vb1 = *(const float4*)(Bp + (size_t)kc * N_DIM + 64);
        }

        // compute: two k8 steps
        #pragma unroll
        for (int ks = 0; ks < 2; ks++) {
            const int k = ks * 8;
            unsigned af[4][4], bf[4][2];
            #pragma unroll
            for (int i = 0; i < 4; i++) {
                const int m0 = wm * 64 + i * 16 + lr;
                af[i][0] = __float_as_uint(As[cur][m0    ][k + lc]);
                af[i][1] = __float_as_uint(As[cur][m0 + 8][k + lc]);
                af[i][2] = __float_as_uint(As[cur][m0    ][k + lc + 4]);
                af[i][3] = __float_as_uint(As[cur][m0 + 8][k + lc + 4]);
            }
            #pragma unroll
            for (int j = 0; j < 4; j++) {
                const int n0 = wn * 32 + j * 8 + lr;
                bf[j][0] = __float_as_uint(Bs[cur][k + lc    ][n0]);
                bf[j][1] = __float_as_uint(Bs[cur][k + lc + 4][n0]);
            }
            #pragma unroll
            for (int i = 0; i < 4; i++)
                #pragma unroll
                for (int j = 0; j < 4; j++)
                    mma_tf32(c[i][j], af[i][0], af[i][1], af[i][2], af[i][3],
                             bf[j][0], bf[j][1]);
        }
    }

    // epilogue: bias + float2 stores (c0,c1 / c2,c3 are adjacent columns)
    #pragma unroll
    for (int i = 0; i < 4; i++) {
        const int row0 = bm + wm * 64 + i * 16 + lr;
        #pragma unroll
        for (int j = 0; j < 4; j++) {
            const int col = bn + wn * 32 + j * 8 + 2 * lc;
            float2 bb = *(const float2*)(bias + col);
            float2 r0, r1;
            r0.x = c[i][j][0] + bb.x;  r0.y = c[i][j][1] + bb.y;
            r1.x = c[i][j][2] + bb.x;  r1.y = c[i][j][3] + bb.y;
            *(float2*)&C[(size_t)row0 * N_DIM + col]       = r0;
            *(float2*)&C[(size_t)(row0 + 8) * N_DIM + col] = r1;
        }
    }
}

__global__ __launch_bounds__(256, 2)
void qkv_gemm(const float* __restrict__ x,
              const float* __restrict__ Wq, const float* __restrict__ bq,
              const float* __restrict__ Wk, const float* __restrict__ bk,
              const float* __restrict__ Wv, const float* __restrict__ bv)
{
    const float* W; const float* b; float* C;
    if (blockIdx.z == 0)      { W = Wq; b = bq; C = g_q; }
    else if (blockIdx.z == 1) { W = Wk; b = bk; C = g_k; }
    else                      { W = Wv; b = bv; C = g_v; }
    gemm_body(x, W, b, C);
}

__global__ __launch_bounds__(256, 2)
void o_gemm(const float* __restrict__ Wo, const float* __restrict__ bo,
            float* __restrict__ out)
{
    gemm_body(g_att, Wo, bo, out);
}

// ---------------- fast exp ----------------
__device__ __forceinline__ float fast_exp(float x)
{
    float z  = x * 1.4426950408889634f;
    float fi = z + 12582912.0f;
    int   n  = __float_as_int(fi) - 0x4B400000;
    float f  = z - (fi - 12582912.0f);
    float p  = 1.3333558146e-3f;
    p = fmaf(p, f, 9.6181291918e-3f);
    p = fmaf(p, f, 5.5504108664e-2f);
    p = fmaf(p, f, 2.4022650695e-1f);
    p = fmaf(p, f, 6.9314718056e-1f);
    p = fmaf(p, f, 1.0f);
    return __int_as_float(__float_as_int(p) + (n << 23));
}

// ---------------- per-(b,s) head-mixing attention ----------------
// phase_shift is analytically dead (cos^2+sin^2=1; imaginary softmax discarded).
__global__ __launch_bounds__(256)
void attention_kernel()
{
    const int m = blockIdx.x;
    const int t = threadIdx.x;

    __shared__ float ks[N_DIM];
    __shared__ float vs[N_DIM];

    const float* qrow = g_q + (size_t)m * N_DIM;
    const float* krow = g_k + (size_t)m * N_DIM;
    const float* vrow = g_v + (size_t)m * N_DIM;

    *(float4*)&ks[t * 8]     = *(const float4*)&krow[t * 8];
    *(float4*)&ks[t * 8 + 4] = *(const float4*)&krow[t * 8 + 4];
    *(float4*)&vs[t * 8]     = *(const float4*)&vrow[t * 8];
    *(float4*)&vs[t * 8 + 4] = *(const float4*)&vrow[t * 8 + 4];

    const float scale = 0.35355339059327373f;   // 1/sqrt(8)
    float4 q0 = *(const float4*)&qrow[t * 8];
    float4 q1 = *(const float4*)&qrow[t * 8 + 4];
    q0.x *= scale; q0.y *= scale; q0.z *= scale; q0.w *= scale;
    q1.x *= scale; q1.y *= scale; q1.z *= scale; q1.w *= scale;

    __syncthreads();

    float sum = 0.0f;
    float4 o0 = {0.f, 0.f, 0.f, 0.f};
    float4 o1 = {0.f, 0.f, 0.f, 0.f};

    #pragma unroll 4
    for (int g = 0; g < HEADS; g++) {
        float4 k0 = *(const float4*)&ks[g * 8];
        float4 k1 = *(const float4*)&ks[g * 8 + 4];
        float s;
        s = q0.x * k0.x;
        s = fmaf(q0.y, k0.y, s);
        s = fmaf(q0.z, k0.z, s);
        s = fmaf(q0.w, k0.w, s);
        s = fmaf(q1.x, k1.x, s);
        s = fmaf(q1.y, k1.y, s);
        s = fmaf(q1.z, k1.z, s);
        s = fmaf(q1.w, k1.w, s);
        float p = fast_exp(s);
        sum += p;
        float4 v0 = *(const float4*)&vs[g * 8];
        float4 v1 = *(const float4*)&vs[g * 8 + 4];
        o0.x = fmaf(p, v0.x, o0.x);  o0.y = fmaf(p, v0.y, o0.y);
        o0.z = fmaf(p, v0.z, o0.z);  o0.w = fmaf(p, v0.w, o0.w);
        o1.x = fmaf(p, v1.x, o1.x);  o1.y = fmaf(p, v1.y, o1.y);
        o1.z = fmaf(p, v1.z, o1.z);  o1.w = fmaf(p, v1.w, o1.w);
    }

    const float inv = 1.0f / sum;
    o0.x *= inv; o0.y *= inv; o0.z *= inv; o0.w *= inv;
    o1.x *= inv; o1.y *= inv; o1.z *= inv; o1.w *= inv;
    *(float4*)&g_att[(size_t)m * N_DIM + t * 8]     = o0;
    *(float4*)&g_att[(size_t)m * N_DIM + t * 8 + 4] = o1;
}

// ---------------- launch ----------------
extern "C" void kernel_launch(void* const* d_in, const int* in_sizes, int n_in,
                              void* d_out, int out_size)
{
    const float* x  = (const float*)d_in[0];
    // d_in[1] = phase_shift: dead.
    const float* Wq = (const float*)d_in[2];
    const float* bq = (const float*)d_in[3];
    const float* Wk = (const float*)d_in[4];
    const float* bk = (const float*)d_in[5];
    const float* Wv = (const float*)d_in[6];
    const float* bv = (const float*)d_in[7];
    const float* Wo = (const float*)d_in[8];
    const float* bo = (const float*)d_in[9];
    float* out = (float*)d_out;

    dim3 gQKV(N_DIM / 128, M_DIM / 128, 3);   // 16 x 8 x 3 = 384 blocks
    dim3 gO  (N_DIM / 128, M_DIM / 128, 1);

    qkv_gemm<<<gQKV, 256>>>(x, Wq, bq, Wk, bk, Wv, bv);
    attention_kernel<<<M_DIM, 256>>>();
    o_gemm<<<gO, 256>>>(Wo, bo, out);
}